// round 3
// baseline (speedup 1.0000x reference)
#include <cuda_runtime.h>
#include <cstdint>

// ---------------------------------------------------------------------------
// GCN_8796093022507: 2-layer GCN collapsed to scalar edge aggregations.
// out[n] = dinv[n] * sum_e g[src]*dinv[src] + b2,
//   g[n] = sum_c dropout2(relu(W1[c]*A[n]+b1[c]))*W2[c]
//   A[n] = dinv[n] * sum_e dropout1(x[src])*dinv[src]
// Dropout masks reproduce JAX threefry2x32 (PARTITIONABLE path, default
// since JAX 0.4.36): 32-bit draw i uses counter (0, i), bits = o0 ^ o1;
// split is foldlike: key_j = outputs of tf(parent, (0, j)).
// ---------------------------------------------------------------------------

#define MAXN 100352
#define KEEP_TH 0x66666800u   // bits < TH  <=>  uniform(bits) < 0.4f
#define INV_KEEP 2.5f         // 1/(1-0.6)

__device__ int   g_deg[MAXN];
__device__ float g_dinv[MAXN];
__device__ float g_p1[MAXN];
__device__ float g_acc1[MAXN];
__device__ float g_p2[MAXN];
__device__ float g_acc2[MAXN];
__device__ int   g_is64;

__host__ __device__ __forceinline__ uint32_t rotl32(uint32_t v, int r) {
#ifdef __CUDA_ARCH__
    return __funnelshift_l(v, v, r);
#else
    return (v << r) | (v >> (32 - r));
#endif
}

// JAX threefry2x32 (20 rounds), key (k0,k1), counter words (x0,x1).
__host__ __device__ __forceinline__ void tf2x32(uint32_t k0, uint32_t k1,
                                                uint32_t x0, uint32_t x1,
                                                uint32_t& o0, uint32_t& o1) {
    const uint32_t k2 = k0 ^ k1 ^ 0x1BD11BDAu;
    x0 += k0; x1 += k1;
#define TFR(r) { x0 += x1; x1 = rotl32(x1, r); x1 ^= x0; }
    TFR(13) TFR(15) TFR(26) TFR(6)
    x0 += k1; x1 += k2 + 1u;
    TFR(17) TFR(29) TFR(16) TFR(24)
    x0 += k2; x1 += k0 + 2u;
    TFR(13) TFR(15) TFR(26) TFR(6)
    x0 += k0; x1 += k1 + 3u;
    TFR(17) TFR(29) TFR(16) TFR(24)
    x0 += k1; x1 += k2 + 4u;
    TFR(13) TFR(15) TFR(26) TFR(6)
    o0 = x0 + k2; o1 = x1 + k0 + 5u;
#undef TFR
}

// Partitionable 32-bit random bits for flat index i: counter (0, i), xor lanes.
__device__ __forceinline__ uint32_t rbits32(uint32_t k0, uint32_t k1, uint32_t i) {
    uint32_t o0, o1;
    tf2x32(k0, k1, 0u, i, o0, o1);
    return o0 ^ o1;
}

// ---------------------------------------------------------------------------
// K0: zero scratch; detect index dtype (int64 <=> all odd 32-bit words zero).
__global__ void k_init(const unsigned int* __restrict__ ei32, int N, long long nwords) {
    int i = blockIdx.x * blockDim.x + threadIdx.x;
    int stride = gridDim.x * blockDim.x;
    for (int n = i; n < N; n += stride) {
        g_deg[n] = 0; g_acc1[n] = 0.f; g_acc2[n] = 0.f;
    }
    if (blockIdx.x == 0) {
        unsigned int v = 0;
        #pragma unroll
        for (int k = 0; k < 8; k++) {
            long long w = 1 + 2LL * (threadIdx.x * 8 + k);
            if (w < nwords) v |= ei32[w];
        }
        int nz = __syncthreads_or(v != 0);
        if (threadIdx.x == 0) g_is64 = nz ? 0 : 1;
    }
}

// ---------------------------------------------------------------------------
// K1: in-degree at dst.
__global__ void k_deg(const void* __restrict__ eiv, long long E) {
    long long base = 4LL * (blockIdx.x * (long long)blockDim.x + threadIdx.x);
    if (base >= E) return;
    int n = (int)(E - base < 4 ? E - base : 4);
    int dsts[4];
    if (g_is64) {
        const long long* e = (const long long*)eiv;
        if (n == 4 && ((E & 1LL) == 0)) {
            longlong2 d0 = *(const longlong2*)(e + E + base);
            longlong2 d1 = *(const longlong2*)(e + E + base + 2);
            dsts[0] = (int)d0.x; dsts[1] = (int)d0.y;
            dsts[2] = (int)d1.x; dsts[3] = (int)d1.y;
        } else {
            for (int i = 0; i < n; i++) dsts[i] = (int)e[E + base + i];
        }
    } else {
        const int* e = (const int*)eiv;
        if (n == 4 && ((E & 3LL) == 0)) {
            int4 d = *(const int4*)(e + E + base);
            dsts[0] = d.x; dsts[1] = d.y; dsts[2] = d.z; dsts[3] = d.w;
        } else {
            for (int i = 0; i < n; i++) dsts[i] = e[E + base + i];
        }
    }
    for (int i = 0; i < n; i++) atomicAdd(&g_deg[dsts[i]], 1);
}

// ---------------------------------------------------------------------------
// K2: dinv, dropout1(x), p1 = hd*dinv.  One thread per node; counter (0, n).
__global__ void k_node1(const float* __restrict__ x, int N,
                        uint32_t k0, uint32_t k1) {
    int n = blockIdx.x * blockDim.x + threadIdx.x;
    if (n >= N) return;
    uint32_t bits = rbits32(k0, k1, (uint32_t)n);
    int di = g_deg[n];
    float d = di > 0 ? rsqrtf((float)di) : 0.f;
    g_dinv[n] = d;
    float h = (bits < KEEP_TH) ? x[n] * INV_KEEP : 0.f;
    g_p1[n] = h * d;
}

// ---------------------------------------------------------------------------
// K3/K5: edge scatter  acc[dst] += p[src].
__global__ void k_edge(const void* __restrict__ eiv, long long E, int which) {
    long long base = 4LL * (blockIdx.x * (long long)blockDim.x + threadIdx.x);
    if (base >= E) return;
    int n = (int)(E - base < 4 ? E - base : 4);
    int srcs[4], dsts[4];
    if (g_is64) {
        const long long* e = (const long long*)eiv;
        if (n == 4 && ((E & 1LL) == 0)) {
            longlong2 s0 = *(const longlong2*)(e + base);
            longlong2 s1 = *(const longlong2*)(e + base + 2);
            longlong2 d0 = *(const longlong2*)(e + E + base);
            longlong2 d1 = *(const longlong2*)(e + E + base + 2);
            srcs[0] = (int)s0.x; srcs[1] = (int)s0.y; srcs[2] = (int)s1.x; srcs[3] = (int)s1.y;
            dsts[0] = (int)d0.x; dsts[1] = (int)d0.y; dsts[2] = (int)d1.x; dsts[3] = (int)d1.y;
        } else {
            for (int i = 0; i < n; i++) { srcs[i] = (int)e[base + i]; dsts[i] = (int)e[E + base + i]; }
        }
    } else {
        const int* e = (const int*)eiv;
        if (n == 4 && ((E & 3LL) == 0)) {
            int4 s = *(const int4*)(e + base);
            int4 d = *(const int4*)(e + E + base);
            srcs[0] = s.x; srcs[1] = s.y; srcs[2] = s.z; srcs[3] = s.w;
            dsts[0] = d.x; dsts[1] = d.y; dsts[2] = d.z; dsts[3] = d.w;
        } else {
            for (int i = 0; i < n; i++) { srcs[i] = e[base + i]; dsts[i] = e[E + base + i]; }
        }
    }
    const float* __restrict__ p = which ? g_p2 : g_p1;
    float* acc = which ? g_acc2 : g_acc1;
    for (int i = 0; i < n; i++) atomicAdd(&acc[dsts[i]], p[srcs[i]]);
}

// ---------------------------------------------------------------------------
// K4: layer-1 epilogue + dropout2 + layer-2 linear.  One thread per (n,c)
//     element, counter (0, 16n+c); reduce 16 channels by shuffles.
__global__ void k_node2(const float* __restrict__ W1, const float* __restrict__ B1,
                        const float* __restrict__ W2, int N,
                        uint32_t k0, uint32_t k1) {
    int t = blockIdx.x * blockDim.x + threadIdx.x;
    if (t >= N * 16) return;
    int n = t >> 4, c = t & 15;
    uint32_t bits = rbits32(k0, k1, (uint32_t)t);
    float dv = g_dinv[n];
    float a = g_acc1[n] * dv;
    float v = fmaxf(fmaf(a, W1[c], B1[c]), 0.f);
    v = (bits < KEEP_TH) ? v * INV_KEEP : 0.f;
    float s = v * W2[c];
    #pragma unroll
    for (int off = 8; off; off >>= 1)
        s += __shfl_down_sync(0xffffffffu, s, off, 16);
    if (c == 0) g_p2[n] = s * dv;
}

// ---------------------------------------------------------------------------
// K6: final output.
__global__ void k_out(float* __restrict__ out, const float* __restrict__ B2, int N) {
    int n = blockIdx.x * blockDim.x + threadIdx.x;
    if (n < N) out[n] = g_acc2[n] * g_dinv[n] + B2[0];
}

// ---------------------------------------------------------------------------
extern "C" void kernel_launch(void* const* d_in, const int* in_sizes, int n_in,
                              void* d_out, int out_size) {
    const float* x  = (const float*)d_in[0];
    const void*  ei = d_in[1];
    const float* W1 = (const float*)d_in[2];
    const float* B1 = (const float*)d_in[3];
    const float* W2 = (const float*)d_in[4];
    const float* B2 = (const float*)d_in[5];
    int N = in_sizes[0];
    long long E = (long long)in_sizes[1] / 2;
    if (N > MAXN) return;

    // Foldlike split of key(42) = (0,42):  key_j = tf(key, (0, j)) outputs.
    uint32_t k1a, k1b, k2a, k2b;
    tf2x32(0u, 42u, 0u, 0u, k1a, k1b);   // key1 = (o0, o1) of counter (0,0)
    tf2x32(0u, 42u, 0u, 1u, k2a, k2b);   // key2 = (o0, o1) of counter (0,1)

    long long nvec = (E + 3) / 4;
    int eb = (int)((nvec + 255) / 256);
    long long nwords = (long long)in_sizes[1];

    k_init<<<(N + 255) / 256, 256>>>((const unsigned int*)ei, N, nwords);
    k_deg<<<eb, 256>>>(ei, E);
    k_node1<<<(N + 255) / 256, 256>>>(x, N, k1a, k1b);
    k_edge<<<eb, 256>>>(ei, E, 0);
    k_node2<<<(N * 16 + 255) / 256, 256>>>(W1, B1, W2, N, k2a, k2b);
    k_edge<<<eb, 256>>>(ei, E, 1);
    k_out<<<(N + 255) / 256, 256>>>((float*)d_out, B2, N);
}

// round 5
// speedup vs baseline: 1.1224x; 1.1224x over previous
#include <cuda_runtime.h>
#include <cstdint>

// ---------------------------------------------------------------------------
// GCN_8796093022507: 2-layer GCN collapsed to scalar edge aggregations.
// out[n] = dinv[n] * sum_e g[src]*dinv[src] + b2,
//   g[n] = sum_c dropout2(relu(W1[c]*A[n]+b1[c]))*W2[c]
//   A[n] = dinv[n] * sum_e dropout1(x[src])*dinv[src]
// Dropout = JAX threefry2x32, partitionable path: bits(i) = o0^o1 of
// tf(key, (0,i)); split is foldlike: key_j = tf(parent,(0,j)).
// Optimizations: skip atomics for exact-zero messages (60% in layer 1),
// threefry only for relu-surviving channels in layer 2, 8 edges/thread.
// ---------------------------------------------------------------------------

#define MAXN 100352
#define KEEP_TH 0x66666800u   // bits < TH  <=>  uniform(bits) < 0.4f
#define INV_KEEP 2.5f         // 1/(1-0.6)

__device__ int   g_deg[MAXN];
__device__ float g_dinv[MAXN];
__device__ float g_p1[MAXN];
__device__ float g_acc1[MAXN];
__device__ float g_p2[MAXN];
__device__ float g_acc2[MAXN];
__device__ int   g_is64;

__host__ __device__ __forceinline__ uint32_t rotl32(uint32_t v, int r) {
#ifdef __CUDA_ARCH__
    return __funnelshift_l(v, v, r);
#else
    return (v << r) | (v >> (32 - r));
#endif
}

// JAX threefry2x32 (20 rounds), key (k0,k1), counter words (x0,x1).
__host__ __device__ __forceinline__ void tf2x32(uint32_t k0, uint32_t k1,
                                                uint32_t x0, uint32_t x1,
                                                uint32_t& o0, uint32_t& o1) {
    const uint32_t k2 = k0 ^ k1 ^ 0x1BD11BDAu;
    x0 += k0; x1 += k1;
#define TFR(r) { x0 += x1; x1 = rotl32(x1, r); x1 ^= x0; }
    TFR(13) TFR(15) TFR(26) TFR(6)
    x0 += k1; x1 += k2 + 1u;
    TFR(17) TFR(29) TFR(16) TFR(24)
    x0 += k2; x1 += k0 + 2u;
    TFR(13) TFR(15) TFR(26) TFR(6)
    x0 += k0; x1 += k1 + 3u;
    TFR(17) TFR(29) TFR(16) TFR(24)
    x0 += k1; x1 += k2 + 4u;
    TFR(13) TFR(15) TFR(26) TFR(6)
    o0 = x0 + k2; o1 = x1 + k0 + 5u;
#undef TFR
}

__device__ __forceinline__ uint32_t rbits32(uint32_t k0, uint32_t k1, uint32_t i) {
    uint32_t o0, o1;
    tf2x32(k0, k1, 0u, i, o0, o1);
    return o0 ^ o1;
}

// ---------------------------------------------------------------------------
// K0: zero scratch; detect index dtype (int64 <=> all odd 32-bit words zero).
__global__ void k_init(const unsigned int* __restrict__ ei32, int N, long long nwords) {
    int i = blockIdx.x * blockDim.x + threadIdx.x;
    int stride = gridDim.x * blockDim.x;
    for (int n = i; n < N; n += stride) {
        g_deg[n] = 0; g_acc1[n] = 0.f; g_acc2[n] = 0.f;
    }
    if (blockIdx.x == 0) {
        unsigned int v = 0;
        #pragma unroll
        for (int k = 0; k < 8; k++) {
            long long w = 1 + 2LL * (threadIdx.x * 8 + k);
            if (w < nwords) v |= ei32[w];
        }
        int nz = __syncthreads_or(v != 0);
        if (threadIdx.x == 0) g_is64 = nz ? 0 : 1;
    }
}

// ---------------------------------------------------------------------------
// K1: in-degree at dst. 8 edges/thread.
__global__ void k_deg(const void* __restrict__ eiv, long long E) {
    long long base = 8LL * (blockIdx.x * (long long)blockDim.x + threadIdx.x);
    if (base >= E) return;
    int dsts[8];
    if (base + 8 <= E) {
        if (g_is64) {
            const long long* e = (const long long*)eiv + E + base;
            #pragma unroll
            for (int k = 0; k < 4; k++) {
                longlong2 d = *(const longlong2*)(e + 2 * k);
                dsts[2 * k] = (int)d.x; dsts[2 * k + 1] = (int)d.y;
            }
        } else {
            const int* e = (const int*)eiv + E + base;
            int4 a = *(const int4*)(e);
            int4 b = *(const int4*)(e + 4);
            dsts[0] = a.x; dsts[1] = a.y; dsts[2] = a.z; dsts[3] = a.w;
            dsts[4] = b.x; dsts[5] = b.y; dsts[6] = b.z; dsts[7] = b.w;
        }
        #pragma unroll
        for (int i = 0; i < 8; i++) atomicAdd(&g_deg[dsts[i]], 1);
    } else {
        int n = (int)(E - base);
        if (g_is64) {
            const long long* e = (const long long*)eiv;
            for (int i = 0; i < n; i++) atomicAdd(&g_deg[(int)e[E + base + i]], 1);
        } else {
            const int* e = (const int*)eiv;
            for (int i = 0; i < n; i++) atomicAdd(&g_deg[e[E + base + i]], 1);
        }
    }
}

// ---------------------------------------------------------------------------
// K2: dinv, dropout1(x), p1 = hd*dinv.  One thread per node; counter (0, n).
__global__ void k_node1(const float* __restrict__ x, int N,
                        uint32_t k0, uint32_t k1) {
    int n = blockIdx.x * blockDim.x + threadIdx.x;
    if (n >= N) return;
    uint32_t bits = rbits32(k0, k1, (uint32_t)n);
    int di = g_deg[n];
    float d = di > 0 ? rsqrtf((float)di) : 0.f;
    g_dinv[n] = d;
    float h = (bits < KEEP_TH) ? x[n] * INV_KEEP : 0.f;
    g_p1[n] = h * d;
}

// ---------------------------------------------------------------------------
// K3/K5: edge scatter  acc[dst] += p[src], skipping exact zeros.
// 8 edges/thread: stream 2x int4 (or 4x longlong2) per array, gather 8,
// then conditional REDs.
__global__ void k_edge(const void* __restrict__ eiv, long long E, int which) {
    long long base = 8LL * (blockIdx.x * (long long)blockDim.x + threadIdx.x);
    if (base >= E) return;
    const float* __restrict__ p = which ? g_p2 : g_p1;
    float* acc = which ? g_acc2 : g_acc1;

    if (base + 8 <= E) {
        int srcs[8], dsts[8];
        if (g_is64) {
            const long long* es = (const long long*)eiv + base;
            const long long* ed = (const long long*)eiv + E + base;
            #pragma unroll
            for (int k = 0; k < 4; k++) {
                longlong2 s = *(const longlong2*)(es + 2 * k);
                longlong2 d = *(const longlong2*)(ed + 2 * k);
                srcs[2 * k] = (int)s.x; srcs[2 * k + 1] = (int)s.y;
                dsts[2 * k] = (int)d.x; dsts[2 * k + 1] = (int)d.y;
            }
        } else {
            const int* es = (const int*)eiv + base;
            const int* ed = (const int*)eiv + E + base;
            int4 s0 = *(const int4*)(es);
            int4 s1 = *(const int4*)(es + 4);
            int4 d0 = *(const int4*)(ed);
            int4 d1 = *(const int4*)(ed + 4);
            srcs[0] = s0.x; srcs[1] = s0.y; srcs[2] = s0.z; srcs[3] = s0.w;
            srcs[4] = s1.x; srcs[5] = s1.y; srcs[6] = s1.z; srcs[7] = s1.w;
            dsts[0] = d0.x; dsts[1] = d0.y; dsts[2] = d0.z; dsts[3] = d0.w;
            dsts[4] = d1.x; dsts[5] = d1.y; dsts[6] = d1.z; dsts[7] = d1.w;
        }
        float v[8];
        #pragma unroll
        for (int i = 0; i < 8; i++) v[i] = __ldg(&p[srcs[i]]);
        #pragma unroll
        for (int i = 0; i < 8; i++)
            if (v[i] != 0.f) atomicAdd(&acc[dsts[i]], v[i]);
    } else {
        int n = (int)(E - base);
        for (int i = 0; i < n; i++) {
            int s, d;
            if (g_is64) {
                const long long* e = (const long long*)eiv;
                s = (int)e[base + i]; d = (int)e[E + base + i];
            } else {
                const int* e = (const int*)eiv;
                s = e[base + i]; d = e[E + base + i];
            }
            float v = p[s];
            if (v != 0.f) atomicAdd(&acc[d], v);
        }
    }
}

// ---------------------------------------------------------------------------
// K4: layer-1 epilogue + dropout2 + layer-2 linear.  One thread per node;
// threefry only for relu-surviving channels (compact bitmask loop).
__global__ void k_node2(const float* __restrict__ W1, const float* __restrict__ B1,
                        const float* __restrict__ W2, int N,
                        uint32_t k0, uint32_t k1) {
    __shared__ float w1[16], b1s[16], w2[16];
    if (threadIdx.x < 16) {
        w1[threadIdx.x] = W1[threadIdx.x];
        b1s[threadIdx.x] = B1[threadIdx.x];
        w2[threadIdx.x] = W2[threadIdx.x];
    }
    __syncthreads();
    int n = blockIdx.x * blockDim.x + threadIdx.x;
    if (n >= N) return;
    float dv = g_dinv[n];
    float a = g_acc1[n] * dv;

    // Build mask of channels with relu(v) > 0; zero channels contribute 0
    // regardless of their dropout bit -> skip threefry for them.
    unsigned mask = 0;
    #pragma unroll
    for (int c = 0; c < 16; c++) {
        float v = fmaf(a, w1[c], b1s[c]);
        mask |= (v > 0.f ? 1u : 0u) << c;
    }
    float s = 0.f;
    unsigned m = mask;
    unsigned base_ctr = (unsigned)n * 16u;
    while (m) {
        int c = __ffs(m) - 1;
        m &= m - 1;
        uint32_t bits = rbits32(k0, k1, base_ctr + (unsigned)c);
        if (bits < KEEP_TH) s += fmaf(a, w1[c], b1s[c]) * w2[c];
    }
    g_p2[n] = s * INV_KEEP * dv;
}

// ---------------------------------------------------------------------------
// K6: final output.
__global__ void k_out(float* __restrict__ out, const float* __restrict__ B2, int N) {
    int n = blockIdx.x * blockDim.x + threadIdx.x;
    if (n < N) out[n] = g_acc2[n] * g_dinv[n] + B2[0];
}

// ---------------------------------------------------------------------------
extern "C" void kernel_launch(void* const* d_in, const int* in_sizes, int n_in,
                              void* d_out, int out_size) {
    const float* x  = (const float*)d_in[0];
    const void*  ei = d_in[1];
    const float* W1 = (const float*)d_in[2];
    const float* B1 = (const float*)d_in[3];
    const float* W2 = (const float*)d_in[4];
    const float* B2 = (const float*)d_in[5];
    int N = in_sizes[0];
    long long E = (long long)in_sizes[1] / 2;
    if (N > MAXN) return;

    // Foldlike split of key(42) = (0,42):  key_j = tf(key, (0, j)) outputs.
    uint32_t k1a, k1b, k2a, k2b;
    tf2x32(0u, 42u, 0u, 0u, k1a, k1b);
    tf2x32(0u, 42u, 0u, 1u, k2a, k2b);

    long long nvec = (E + 7) / 8;
    int eb = (int)((nvec + 255) / 256);
    long long nwords = (long long)in_sizes[1];

    k_init<<<(N + 255) / 256, 256>>>((const unsigned int*)ei, N, nwords);
    k_deg<<<eb, 256>>>(ei, E);
    k_node1<<<(N + 255) / 256, 256>>>(x, N, k1a, k1b);
    k_edge<<<eb, 256>>>(ei, E, 0);
    k_node2<<<(N + 255) / 256, 256>>>(W1, B1, W2, N, k2a, k2b);
    k_edge<<<eb, 256>>>(ei, E, 1);
    k_out<<<(N + 255) / 256, 256>>>((float*)d_out, B2, N);
}